// round 14
// baseline (speedup 1.0000x reference)
#include <cuda_runtime.h>
#include <cuda_bf16.h>
#include <math.h>
#include <stdint.h>

// ---------------- problem constants ----------------
#define Bb   4
#define Cc   128
#define Tt   16
#define Hh   56
#define Ww   56
#define THW  50176      // Tt*Hh*Ww
#define TOK  200704     // Bb*THW
#define NTOK 196        // 4*7*7
#define HID  512
#define NPAD 208        // 13*16
#define SSTR 40         // attn smem row stride in bf16

// ---------------- scratch (device globals) ----------------
__device__ __nv_bfloat16 g_win [(size_t)TOK * Cc];    // BN'd windows (bf16, window order)
__device__ __nv_bfloat16 g_qkv [(size_t)TOK * 384];   // qkv (bf16, window order)
__device__ __nv_bfloat16 g_attn[(size_t)TOK * Cc];    // attention out (bf16, window order)
__device__ float         g_xtok[(size_t)TOK * Cc];    // raw x (fp32, token order)
// transposed bf16 weights [N][K]
__device__ __nv_bfloat16 g_wq[384 * 128];
__device__ __nv_bfloat16 g_wp[128 * 128];
__device__ __nv_bfloat16 g_w1[512 * 128];
__device__ __nv_bfloat16 g_w2[128 * 512];

// ---------------- helpers ----------------
__device__ __forceinline__ uint32_t smem_u32(const void* p) {
    uint32_t a;
    asm("{ .reg .u64 t; cvta.to.shared.u64 t, %1; cvt.u32.u64 %0, t; }" : "=r"(a) : "l"(p));
    return a;
}
__device__ __forceinline__ void ldsm4(uint32_t* r, uint32_t addr) {
    asm volatile("ldmatrix.sync.aligned.m8n8.x4.shared.b16 {%0,%1,%2,%3}, [%4];"
        : "=r"(r[0]), "=r"(r[1]), "=r"(r[2]), "=r"(r[3]) : "r"(addr));
}
__device__ __forceinline__ void ldsm4t(uint32_t* r, uint32_t addr) {
    asm volatile("ldmatrix.sync.aligned.m8n8.x4.trans.shared.b16 {%0,%1,%2,%3}, [%4];"
        : "=r"(r[0]), "=r"(r[1]), "=r"(r[2]), "=r"(r[3]) : "r"(addr));
}
__device__ __forceinline__ void mma_bf16(float* d, const uint32_t* a, uint32_t b0, uint32_t b1) {
    asm volatile(
        "mma.sync.aligned.m16n8k16.row.col.f32.bf16.bf16.f32 "
        "{%0,%1,%2,%3}, {%4,%5,%6,%7}, {%8,%9}, {%0,%1,%2,%3};"
        : "+f"(d[0]), "+f"(d[1]), "+f"(d[2]), "+f"(d[3])
        : "r"(a[0]), "r"(a[1]), "r"(a[2]), "r"(a[3]), "r"(b0), "r"(b1));
}
__device__ __forceinline__ uint32_t pk_bf2(float x, float y) {
    __nv_bfloat162 h = __floats2bfloat162_rn(x, y);
    return *(uint32_t*)&h;
}
__device__ __forceinline__ float gelu_exact(float v) {
    return 0.5f * v * (1.0f + erff(v * 0.7071067811865475f));
}
__device__ __forceinline__ void cpa16(uint32_t dst, const void* src) {
    asm volatile("cp.async.cg.shared.global [%0], [%1], 16;" :: "r"(dst), "l"(src));
}

// 128x128x128 HMMA accumulate: rows at stride 272B. acc flattened [16][4].
__device__ __forceinline__ void tile_mma_128(
    uint32_t sA, uint32_t sW, float (*acc)[4],
    int wm, int wn, int aRow, int aKH, int bRow, int bKH)
{
#pragma unroll
    for (int ks = 0; ks < 8; ks++) {
        const int kk = ks * 16;
        uint32_t a[2][4], b[4][4];
#pragma unroll
        for (int mt = 0; mt < 2; mt++)
            ldsm4(a[mt], sA + (wm * 32 + mt * 16 + aRow) * 272 + (kk + aKH * 8) * 2);
#pragma unroll
        for (int np = 0; np < 4; np++)
            ldsm4(b[np], sW + (wn * 64 + np * 16 + bRow) * 272 + (kk + bKH * 8) * 2);
#pragma unroll
        for (int mt = 0; mt < 2; mt++)
#pragma unroll
            for (int nt = 0; nt < 8; nt++)
                mma_bf16(acc[mt * 8 + nt], a[mt], b[nt >> 1][(nt & 1) * 2],
                         b[nt >> 1][(nt & 1) * 2 + 1]);
    }
}

// ============================================================
// Weight transpose + bf16 convert: W[K][N] -> Wt[N][K] bf16
// ============================================================
__global__ __launch_bounds__(256) void wprep_kernel(
    const float* __restrict__ qkv_w, const float* __restrict__ proj_w,
    const float* __restrict__ fc1_w, const float* __restrict__ fc2_w)
{
    int i = blockIdx.x * 256 + threadIdx.x;
    if (i < 49152) {                       // qkv: 384x128
        int n = i >> 7, k = i & 127;
        g_wq[i] = __float2bfloat16_rn(qkv_w[k * 384 + n]);
    } else if (i < 65536) {                // proj: 128x128
        int j = i - 49152; int n = j >> 7, k = j & 127;
        g_wp[j] = __float2bfloat16_rn(proj_w[k * 128 + n]);
    } else if (i < 131072) {               // fc1: 512x128
        int j = i - 65536; int n = j >> 7, k = j & 127;
        g_w1[j] = __float2bfloat16_rn(fc1_w[k * 512 + n]);
    } else if (i < 196608) {               // fc2: 128x512
        int j = i - 131072; int n = j >> 9, k = j & 511;
        g_w2[j] = __float2bfloat16_rn(fc2_w[k * 128 + n]);
    }
}

// ============================================================
// BN + window partition (bf16) + token-major raw copy (fp32)
// ============================================================
__global__ __launch_bounds__(256) void bn_window_kernel(
    const float* __restrict__ x, const float* __restrict__ gamma,
    const float* __restrict__ beta, const float* __restrict__ mean,
    const float* __restrict__ var, __nv_bfloat16* __restrict__ win,
    float* __restrict__ xtok)
{
    __shared__ float rawS[32][57];
    __shared__ float bnS[32][57];
    const int gx = blockIdx.x;
    const int t = gx / 56, h = gx % 56;
    const int c0 = blockIdx.y * 32;
    const int b = blockIdx.z;
    const int tid = threadIdx.x;

#pragma unroll
    for (int it = 0; it < 7; it++) {
        int idx = tid + it * 256;
        int i = idx / 56, j = idx % 56;
        int c = c0 + i;
        size_t off = ((((size_t)b * Cc + c) * Tt + t) * Hh + h) * Ww + j;
        float v = x[off];
        rawS[i][j] = v;
        float inv = rsqrtf(var[c] + 1e-5f);
        bnS[i][j] = (v - mean[c]) * (inv * gamma[c]) + beta[c];
    }
    __syncthreads();

    const int tblk = t >> 2, wt = t & 3;
    const int hblk = h / 7, wh = h % 7;
#pragma unroll
    for (int it = 0; it < 7; it++) {
        int idx = tid + it * 256;
        int i = idx & 31, j = idx >> 5;
        int wblk = j / 7, ww2 = j % 7;
        int widx = ((b * 4 + tblk) * 8 + hblk) * 8 + wblk;
        int n = (wt * 7 + wh) * 7 + ww2;
        win[((size_t)widx * NTOK + n) * Cc + c0 + i] = __float2bfloat16_rn(bnS[i][j]);
        size_t tok = (size_t)b * THW + ((size_t)t * Hh + h) * Ww + j;
        xtok[tok * Cc + c0 + i] = rawS[i][j];
    }
}

// ============================================================
// QKV GEMM: A staged ONCE per CTA, in-CTA loop over 3 N-blocks,
// B halves (128n x 64k) double-buffered. grid 1568, 8 warps 4Mx2N.
// ============================================================
__global__ __launch_bounds__(256) void qkv_gemm(
    const __nv_bfloat16* __restrict__ A, const __nv_bfloat16* __restrict__ Bm,
    const float* __restrict__ bias, __nv_bfloat16* __restrict__ outq)
{
    extern __shared__ char dsm[];
    const uint32_t sA = smem_u32(dsm);            // [128][136] bf16 (272B rows)
    const uint32_t sB0 = sA + 34816;              // [128][72] bf16 (144B rows)
    const uint32_t sB1 = sB0 + 18432;
    const int tid = threadIdx.x;
    const int rb = blockIdx.x * 128;
    const int lane = tid & 31, wid = tid >> 5;
    const int wm = wid >> 1, wn = wid & 1;

    const int aRow = lane & 15, aKH = lane >> 4;
    const int bRow = ((lane >> 4) << 3) + (lane & 7);
    const int bKH = (lane >> 3) & 1;
    const int gid = lane >> 2, tig = lane & 3;

#pragma unroll
    for (int it = 0; it < 8; it++) {
        int idx = tid + it * 256;
        int row = idx >> 4, c8 = idx & 15;
        cpa16(sA + row * 272 + c8 * 16, A + (size_t)(rb + row) * Cc + c8 * 8);
    }
    asm volatile("cp.async.commit_group;");

    auto load_half = [&](int i, uint32_t buf) {   // i = n*2 + kh
        const int n = i >> 1, kh = i & 1;
#pragma unroll
        for (int it = 0; it < 4; it++) {
            int idx = tid + it * 256;
            int row = idx >> 3, c8 = idx & 7;
            cpa16(buf + row * 144 + c8 * 16,
                  Bm + (size_t)(n * 128 + row) * Cc + kh * 64 + c8 * 8);
        }
        asm volatile("cp.async.commit_group;");
    };
    load_half(0, sB0);

    float acc[16][4];
#pragma unroll
    for (int u = 0; u < 16; u++)
#pragma unroll
        for (int j = 0; j < 4; j++) acc[u][j] = 0.f;

    for (int i = 0; i < 6; i++) {
        const int kh = i & 1;
        __syncthreads();
        if (i < 5) load_half(i + 1, (i + 1) & 1 ? sB1 : sB0);
        if (i < 5) { asm volatile("cp.async.wait_group 1;"); }
        else       { asm volatile("cp.async.wait_group 0;"); }
        __syncthreads();

        const uint32_t bB = (i & 1) ? sB1 : sB0;
#pragma unroll
        for (int ks = 0; ks < 4; ks++) {
            const int kkA = kh * 64 + ks * 16, kkB = ks * 16;
            uint32_t a[2][4], b[4][4];
#pragma unroll
            for (int mt = 0; mt < 2; mt++)
                ldsm4(a[mt], sA + (wm * 32 + mt * 16 + aRow) * 272 + (kkA + aKH * 8) * 2);
#pragma unroll
            for (int np = 0; np < 4; np++)
                ldsm4(b[np], bB + (wn * 64 + np * 16 + bRow) * 144 + (kkB + bKH * 8) * 2);
#pragma unroll
            for (int mt = 0; mt < 2; mt++)
#pragma unroll
                for (int nt = 0; nt < 8; nt++)
                    mma_bf16(acc[mt * 8 + nt], a[mt], b[nt >> 1][(nt & 1) * 2],
                             b[nt >> 1][(nt & 1) * 2 + 1]);
        }

        if (kh == 1) {
            const int n = i >> 1;
#pragma unroll
            for (int mt = 0; mt < 2; mt++) {
#pragma unroll
                for (int half = 0; half < 2; half++) {
                    const int R = rb + wm * 32 + mt * 16 + half * 8 + gid;
                    __nv_bfloat16* po = outq + (size_t)R * 384 + n * 128;
#pragma unroll
                    for (int nt = 0; nt < 8; nt++) {
                        int c = wn * 64 + nt * 8 + tig * 2;
                        float v0 = acc[mt * 8 + nt][half * 2]     + bias[n * 128 + c];
                        float v1 = acc[mt * 8 + nt][half * 2 + 1] + bias[n * 128 + c + 1];
                        *(__nv_bfloat162*)(po + c) = __floats2bfloat162_rn(v0, v1);
                    }
                }
            }
#pragma unroll
            for (int u = 0; u < 16; u++)
#pragma unroll
                for (int j = 0; j < 4; j++) acc[u][j] = 0.f;
        }
    }
}

// ============================================================
// FUSED proj + LayerNorm + MLP + residuals + transposed store.
// One CTA per 128 window-order rows (grid 1568, 256 thr, 104KB smem,
// 2 CTA/SM). y stays in oacc; f in smem. Phase C hides w2 loads
// behind the gelu/erf epilogue.
// ============================================================
__global__ __launch_bounds__(256, 1) void pm_kernel(
    const __nv_bfloat16* __restrict__ A, const __nv_bfloat16* __restrict__ Wp,
    const float* __restrict__ pbias, const float* __restrict__ xres,
    const float* __restrict__ lng, const float* __restrict__ lnb,
    const __nv_bfloat16* __restrict__ w1, const __nv_bfloat16* __restrict__ w2,
    const float* __restrict__ b1, const float* __restrict__ b2,
    float* __restrict__ out)
{
    extern __shared__ char dsm[];
    const uint32_t sF = smem_u32(dsm);            // [128][136] bf16
    const uint32_t sW = sF + 34816;               // weight chunk buffer
    const uint32_t sH = sW + 34816;               // hidden tile
    float2* red = (float2*)(dsm + 104448);        // [128][2]
    const int tid = threadIdx.x;
    const int rb = blockIdx.x * 128;
    const int lane = tid & 31, wid = tid >> 5;
    const int wm = wid >> 1, wn = wid & 1;

    const int aRow = lane & 15, aKH = lane >> 4;
    const int bRow = ((lane >> 4) << 3) + (lane & 7);
    const int bKH = (lane >> 3) & 1;
    const int gid = lane >> 2, tig = lane & 3;
    const int ldRow = tid >> 2, ldC = tid & 3;

    // ---------- phase A: proj GEMM (2-stage, K-chunk 32; aliases sF/sW) ----------
    const uint32_t pA = sF, pB = sF + 20480;
    float oacc[16][4];
#pragma unroll
    for (int u = 0; u < 16; u++)
#pragma unroll
        for (int j = 0; j < 4; j++) oacc[u][j] = 0.f;

    auto preload = [&](int ch) {
        const int b = ch & 1, k0 = ch * 32;
#pragma unroll
        for (int p = 0; p < 2; p++) {
            int row = ldRow + p * 64;
            uint32_t off = (uint32_t)(b * 10240 + row * 80 + ldC * 16);
            cpa16(pA + off, A + (size_t)(rb + row) * Cc + k0 + ldC * 8);
            cpa16(pB + off, Wp + (size_t)row * Cc + k0 + ldC * 8);
        }
        asm volatile("cp.async.commit_group;");
    };

    preload(0);
    for (int ch = 0; ch < 4; ch++) {
        if (ch + 1 < 4) {
            preload(ch + 1);
            asm volatile("cp.async.wait_group 1;");
        } else {
            asm volatile("cp.async.wait_group 0;");
        }
        __syncthreads();
        const uint32_t bA = pA + (ch & 1) * 10240;
        const uint32_t bB = pB + (ch & 1) * 10240;
#pragma unroll
        for (int ks = 0; ks < 2; ks++) {
            const int kk = ks * 16;
            uint32_t a[2][4], b[4][4];
#pragma unroll
            for (int mt = 0; mt < 2; mt++)
                ldsm4(a[mt], bA + (wm * 32 + mt * 16 + aRow) * 80 + (kk + aKH * 8) * 2);
#pragma unroll
            for (int np = 0; np < 4; np++)
                ldsm4(b[np], bB + (wn * 64 + np * 16 + bRow) * 80 + (kk + bKH * 8) * 2);
#pragma unroll
            for (int mt = 0; mt < 2; mt++)
#pragma unroll
                for (int nt = 0; nt < 8; nt++)
                    mma_bf16(oacc[mt * 8 + nt], a[mt], b[nt >> 1][(nt & 1) * 2],
                             b[nt >> 1][(nt & 1) * 2 + 1]);
        }
        __syncthreads();
    }

    // ---------- phase B: y = proj + bias + x (stays in oacc); LN -> f in sF ----------
    size_t toks[2][2];
    float rsum[2][2], rsq[2][2];
#pragma unroll
    for (int mt = 0; mt < 2; mt++) {
#pragma unroll
        for (int half = 0; half < 2; half++) {
            const int R = rb + wm * 32 + mt * 16 + half * 8 + gid;
            unsigned r = (unsigned)R;
            unsigned widx = r / 196u, nl = r - widx * 196u;
            unsigned wblk = widx & 7u, hblk = (widx >> 3) & 7u;
            unsigned tblk = (widx >> 6) & 3u, bbx = widx >> 8;
            unsigned wt = nl / 49u, rem = nl - wt * 49u;
            unsigned wh = rem / 7u, w2i = rem - wh * 7u;
            unsigned th = tblk * 4 + wt, hp = hblk * 7 + wh, wp = wblk * 7 + w2i;
            size_t tok = (size_t)bbx * THW + ((size_t)th * Hh + hp) * Ww + wp;
            toks[mt][half] = tok;
            const float* pr = xres + tok * Cc;
            float s = 0.f, q = 0.f;
#pragma unroll
            for (int nt = 0; nt < 8; nt++) {
                int c = wn * 64 + nt * 8 + tig * 2;
                float2 xr = *(const float2*)(pr + c);
                float y0 = oacc[mt * 8 + nt][half * 2]     + pbias[c]     + xr.x;
                float y1 = oacc[mt * 8 + nt][half * 2 + 1] + pbias[c + 1] + xr.y;
                oacc[mt * 8 + nt][half * 2]     = y0;
                oacc[mt * 8 + nt][half * 2 + 1] = y1;
                s += y0 + y1;
                q += y0 * y0 + y1 * y1;
            }
            rsum[mt][half] = s; rsq[mt][half] = q;
        }
    }
#pragma unroll
    for (int mt = 0; mt < 2; mt++)
#pragma unroll
        for (int half = 0; half < 2; half++) {
            rsum[mt][half] += __shfl_xor_sync(0xffffffffu, rsum[mt][half], 1);
            rsum[mt][half] += __shfl_xor_sync(0xffffffffu, rsum[mt][half], 2);
            rsq[mt][half]  += __shfl_xor_sync(0xffffffffu, rsq[mt][half], 1);
            rsq[mt][half]  += __shfl_xor_sync(0xffffffffu, rsq[mt][half], 2);
        }
    __syncthreads();
    if (tig == 0) {
#pragma unroll
        for (int mt = 0; mt < 2; mt++)
#pragma unroll
            for (int half = 0; half < 2; half++) {
                int r = wm * 32 + mt * 16 + half * 8 + gid;
                float2 v; v.x = rsum[mt][half]; v.y = rsq[mt][half];
                red[r * 2 + wn] = v;
            }
    }
    __syncthreads();
#pragma unroll
    for (int mt = 0; mt < 2; mt++) {
#pragma unroll
        for (int half = 0; half < 2; half++) {
            int r = wm * 32 + mt * 16 + half * 8 + gid;
            float2 p0 = red[r * 2], p1 = red[r * 2 + 1];
            float mu = (p0.x + p1.x) * (1.f / 128.f);
            float var = (p0.y + p1.y) * (1.f / 128.f) - mu * mu;
            float inv = rsqrtf(var + 1e-5f);
#pragma unroll
            for (int nt = 0; nt < 8; nt++) {
                int c = wn * 64 + nt * 8 + tig * 2;
                float2 gg = *(const float2*)(lng + c);
                float2 bb = *(const float2*)(lnb + c);
                float f0 = (oacc[mt * 8 + nt][half * 2]     - mu) * inv * gg.x + bb.x;
                float f1 = (oacc[mt * 8 + nt][half * 2 + 1] - mu) * inv * gg.y + bb.y;
                uint32_t pk = pk_bf2(f0, f1);
                asm volatile("st.shared.b32 [%0], %1;"
                             :: "r"(sF + r * 272 + c * 2), "r"(pk));
            }
        }
    }
    __syncthreads();

    // ---------- phase C: MLP, oacc (=y) accumulates fc2 ----------
    for (int nc = 0; nc < 4; nc++) {
        // w1 chunk
#pragma unroll
        for (int it = 0; it < 8; it++) {
            int idx = tid + it * 256;
            int row = idx >> 4, c8 = idx & 15;
            cpa16(sW + row * 272 + c8 * 16,
                  w1 + (size_t)(nc * 128 + row) * Cc + c8 * 8);
        }
        asm volatile("cp.async.commit_group;");
        asm volatile("cp.async.wait_group 0;");
        __syncthreads();

        float hacc[16][4];
#pragma unroll
        for (int u = 0; u < 16; u++)
#pragma unroll
            for (int j = 0; j < 4; j++) hacc[u][j] = 0.f;
        tile_mma_128(sF, sW, hacc, wm, wn, aRow, aKH, bRow, bKH);
        __syncthreads();          // all warps done reading w1 from sW

        // issue w2 load NOW — hides behind the erf-heavy gelu stores below
#pragma unroll
        for (int it = 0; it < 8; it++) {
            int idx = tid + it * 256;
            int row = idx >> 4, c8 = idx & 15;
            cpa16(sW + row * 272 + c8 * 16,
                  w2 + (size_t)row * HID + nc * 128 + c8 * 8);
        }
        asm volatile("cp.async.commit_group;");

#pragma unroll
        for (int mt = 0; mt < 2; mt++) {
#pragma unroll
            for (int half = 0; half < 2; half++) {
                int row = wm * 32 + mt * 16 + half * 8 + gid;
#pragma unroll
                for (int nt = 0; nt < 8; nt++) {
                    int c = wn * 64 + nt * 8 + tig * 2;
                    float v0 = gelu_exact(hacc[mt * 8 + nt][half * 2]     + b1[nc * 128 + c]);
                    float v1 = gelu_exact(hacc[mt * 8 + nt][half * 2 + 1] + b1[nc * 128 + c + 1]);
                    uint32_t pk = pk_bf2(v0, v1);
                    asm volatile("st.shared.b32 [%0], %1;"
                                 :: "r"(sH + row * 272 + c * 2), "r"(pk));
                }
            }
        }
        asm volatile("cp.async.wait_group 0;");
        __syncthreads();          // h visible + w2 ready

        tile_mma_128(sH, sW, oacc, wm, wn, aRow, aKH, bRow, bKH);
        __syncthreads();
    }

    // ---------- phase D: out = oacc + b2, transposed store (B,C,THW) ----------
#pragma unroll
    for (int mt = 0; mt < 2; mt++) {
#pragma unroll
        for (int half = 0; half < 2; half++) {
            size_t tok = toks[mt][half];
            unsigned bq = (unsigned)(tok / (size_t)THW);
            unsigned thw = (unsigned)(tok - (size_t)bq * THW);
#pragma unroll
            for (int nt = 0; nt < 8; nt++) {
                int c = wn * 64 + nt * 8 + tig * 2;
                out[(size_t)(bq * Cc + c) * THW + thw] =
                    oacc[mt * 8 + nt][half * 2] + b2[c];
                out[(size_t)(bq * Cc + c + 1) * THW + thw] =
                    oacc[mt * 8 + nt][half * 2 + 1] + b2[c + 1];
            }
        }
    }
}

// ============================================================
// HMMA attention: one CTA per (window, head), 8 warps (256 thr).
// Tiles striped wid..12 step 8 -> critical path 2 tiles (was 4);
// occupancy ~75% (was 31.6%). exp2f with log2e folded into scale.
// ============================================================
__global__ __launch_bounds__(256) void attn_mma_kernel(
    const __nv_bfloat16* __restrict__ qkv, __nv_bfloat16* __restrict__ outp)
{
    __shared__ __nv_bfloat16 Ks[NPAD * SSTR];
    __shared__ __nv_bfloat16 Vs[NPAD * SSTR];
    const int widx = blockIdx.x, hh = blockIdx.y;
    const size_t base = (size_t)widx * NTOK * 384 + hh * 32;
    const int tid = threadIdx.x;
    const int lane = tid & 31, wid = tid >> 5;

    for (int idx = tid; idx < 3136; idx += 256) {
        int row = idx >> 4, u = idx & 15;
        const uint32_t* src = (const uint32_t*)(qkv + base + (size_t)row * 384);
        *(uint32_t*)(Ks + row * SSTR + u * 2) = src[64 + u];
        *(uint32_t*)(Vs + row * SSTR + u * 2) = src[128 + u];
    }
    if (tid < 192) {                       // zero pad rows 196..207 (12*16=192)
        int row = 196 + (tid >> 4), u = tid & 15;
        *(uint32_t*)(Ks + row * SSTR + u * 2) = 0;
        *(uint32_t*)(Vs + row * SSTR + u * 2) = 0;
    }
    __syncthreads();

    const int g = lane >> 2, tig = lane & 3;
    const int bRow = ((lane >> 4) << 3) + (lane & 7), bKH = (lane >> 3) & 1;
    const int vKrow = (lane & 7) + ((lane >> 3) & 1) * 8;
    const int vNh = ((lane >> 4) & 1) * 8;
    const float sc2 = 0.17677669529663688f * 1.4426950408889634f;  // 1/sqrt(32) * log2(e)

    for (int mt = wid; mt < 13; mt += 8) {
        const int m0 = mt * 16;
        int r0 = m0 + g;     if (r0 > 195) r0 = 195;
        int r1 = m0 + g + 8; if (r1 > 195) r1 = 195;
        const __nv_bfloat16* q0 = qkv + base + (size_t)r0 * 384 + tig * 2;
        const __nv_bfloat16* q1 = qkv + base + (size_t)r1 * 384 + tig * 2;
        uint32_t qa[2][4];
        qa[0][0] = *(const uint32_t*)(q0);
        qa[0][1] = *(const uint32_t*)(q1);
        qa[0][2] = *(const uint32_t*)(q0 + 8);
        qa[0][3] = *(const uint32_t*)(q1 + 8);
        qa[1][0] = *(const uint32_t*)(q0 + 16);
        qa[1][1] = *(const uint32_t*)(q1 + 16);
        qa[1][2] = *(const uint32_t*)(q0 + 24);
        qa[1][3] = *(const uint32_t*)(q1 + 24);

        float oacc[4][4];
#pragma unroll
        for (int nt = 0; nt < 4; nt++)
#pragma unroll
            for (int j = 0; j < 4; j++) oacc[nt][j] = 0.f;
        float rs0 = 0.f, rs1 = 0.f;

        for (int ks = 0; ks < 13; ks++) {
            uint32_t kb0[4], kb1[4];
            ldsm4(kb0, smem_u32(Ks + (ks * 16 + bRow) * SSTR + bKH * 8));
            ldsm4(kb1, smem_u32(Ks + (ks * 16 + bRow) * SSTR + 16 + bKH * 8));

            float s0[4] = {0.f, 0.f, 0.f, 0.f}, s1[4] = {0.f, 0.f, 0.f, 0.f};
            mma_bf16(s0, qa[0], kb0[0], kb0[1]);
            mma_bf16(s0, qa[1], kb1[0], kb1[1]);
            mma_bf16(s1, qa[0], kb0[2], kb0[3]);
            mma_bf16(s1, qa[1], kb1[2], kb1[3]);

            float e0[4], e1[4];
#pragma unroll
            for (int j = 0; j < 4; j++) {
                e0[j] = exp2f(s0[j] * sc2);
                e1[j] = exp2f(s1[j] * sc2);
            }
            if (ks == 12) {                         // mask cols >= 196
#pragma unroll
                for (int j = 0; j < 4; j++) e1[j] = 0.f;
                if (tig >= 2) {
#pragma unroll
                    for (int j = 0; j < 4; j++) e0[j] = 0.f;
                }
            }
            rs0 += e0[0] + e0[1] + e1[0] + e1[1];
            rs1 += e0[2] + e0[3] + e1[2] + e1[3];

            uint32_t pa[4];
            pa[0] = pk_bf2(e0[0], e0[1]);
            pa[1] = pk_bf2(e0[2], e0[3]);
            pa[2] = pk_bf2(e1[0], e1[1]);
            pa[3] = pk_bf2(e1[2], e1[3]);

            uint32_t vb0[4], vb1[4];
            uint32_t va = smem_u32(Vs + (ks * 16 + vKrow) * SSTR + vNh);
            ldsm4t(vb0, va);
            ldsm4t(vb1, va + 32);
            mma_bf16(oacc[0], pa, vb0[0], vb0[1]);
            mma_bf16(oacc[1], pa, vb0[2], vb0[3]);
            mma_bf16(oacc[2], pa, vb1[0], vb1[1]);
            mma_bf16(oacc[3], pa, vb1[2], vb1[3]);
        }

        rs0 += __shfl_xor_sync(0xffffffffu, rs0, 1);
        rs0 += __shfl_xor_sync(0xffffffffu, rs0, 2);
        rs1 += __shfl_xor_sync(0xffffffffu, rs1, 1);
        rs1 += __shfl_xor_sync(0xffffffffu, rs1, 2);
        float i0 = 1.f / rs0, i1 = 1.f / rs1;

        const int w0 = m0 + g, w1 = m0 + g + 8;
        if (w0 < NTOK) {
            __nv_bfloat16* p = outp + ((size_t)widx * NTOK + w0) * Cc + hh * 32 + tig * 2;
#pragma unroll
            for (int nt = 0; nt < 4; nt++)
                *(__nv_bfloat162*)(p + nt * 8) =
                    __floats2bfloat162_rn(oacc[nt][0] * i0, oacc[nt][1] * i0);
        }
        if (w1 < NTOK) {
            __nv_bfloat16* p = outp + ((size_t)widx * NTOK + w1) * Cc + hh * 32 + tig * 2;
#pragma unroll
            for (int nt = 0; nt < 4; nt++)
                *(__nv_bfloat162*)(p + nt * 8) =
                    __floats2bfloat162_rn(oacc[nt][2] * i1, oacc[nt][3] * i1);
        }
    }
}

// ============================================================
// Launch
// ============================================================
extern "C" void kernel_launch(void* const* d_in, const int* in_sizes, int n_in,
                              void* d_out, int out_size)
{
    const float* x      = (const float*)d_in[0];
    const float* bn_g   = (const float*)d_in[1];
    const float* bn_b   = (const float*)d_in[2];
    const float* bn_m   = (const float*)d_in[3];
    const float* bn_v   = (const float*)d_in[4];
    const float* qkv_w  = (const float*)d_in[5];
    const float* qkv_b  = (const float*)d_in[6];
    const float* proj_w = (const float*)d_in[7];
    const float* proj_b = (const float*)d_in[8];
    const float* ln_g   = (const float*)d_in[9];
    const float* ln_b   = (const float*)d_in[10];
    const float* fc1_w  = (const float*)d_in[11];
    const float* fc1_b  = (const float*)d_in[12];
    const float* fc2_w  = (const float*)d_in[13];
    const float* fc2_b  = (const float*)d_in[14];
    float* out = (float*)d_out;

    __nv_bfloat16 *p_win, *p_qkv, *p_attn, *p_wq, *p_wp, *p_w1, *p_w2;
    float *p_xtok;
    cudaGetSymbolAddress((void**)&p_win, g_win);
    cudaGetSymbolAddress((void**)&p_qkv, g_qkv);
    cudaGetSymbolAddress((void**)&p_attn, g_attn);
    cudaGetSymbolAddress((void**)&p_wq, g_wq);
    cudaGetSymbolAddress((void**)&p_wp, g_wp);
    cudaGetSymbolAddress((void**)&p_w1, g_w1);
    cudaGetSymbolAddress((void**)&p_w2, g_w2);
    cudaGetSymbolAddress((void**)&p_xtok, g_xtok);

    const int QSM = 71680;       // qkv: A once + 2 B-half buffers
    const int FSM = 106496;      // fused pm: sF + sW + sH + red
    cudaFuncSetAttribute(qkv_gemm, cudaFuncAttributeMaxDynamicSharedMemorySize, QSM);
    cudaFuncSetAttribute(pm_kernel, cudaFuncAttributeMaxDynamicSharedMemorySize, FSM);

    // 0. weight transpose + bf16
    wprep_kernel<<<768, 256>>>(qkv_w, proj_w, fc1_w, fc2_w);

    // 1. BN + window partition (bf16) + raw token copy (fp32)
    bn_window_kernel<<<dim3(896, 4, 4), 256>>>(x, bn_g, bn_b, bn_m, bn_v, p_win, p_xtok);

    // 2. QKV GEMM (A staged once, N-loop in-CTA)
    qkv_gemm<<<1568, 256, QSM>>>(p_win, p_wq, qkv_b, p_qkv);

    // 3. Windowed attention (HMMA, 8 warps)
    attn_mma_kernel<<<dim3(1024, 4), 256>>>(p_qkv, p_attn);

    // 4. FUSED proj + LN + MLP + residuals + transposed store
    pm_kernel<<<1568, 256, FSM>>>(p_attn, p_wp, proj_b, p_xtok, ln_g, ln_b,
                                  p_w1, p_w2, fc1_b, fc2_b, out);
}

// round 15
// speedup vs baseline: 1.0343x; 1.0343x over previous
#include <cuda_runtime.h>
#include <cuda_bf16.h>
#include <math.h>
#include <stdint.h>

// ---------------- problem constants ----------------
#define Bb   4
#define Cc   128
#define Tt   16
#define Hh   56
#define Ww   56
#define THW  50176      // Tt*Hh*Ww
#define TOK  200704     // Bb*THW
#define NTOK 196        // 4*7*7
#define HID  512
#define NPAD 208        // 13*16
#define SSTR 40         // attn smem row stride in bf16

// ---------------- scratch (device globals) ----------------
__device__ __nv_bfloat16 g_win [(size_t)TOK * Cc];    // BN'd windows (bf16, window order)
__device__ __nv_bfloat16 g_qkv [(size_t)TOK * 384];   // qkv (bf16, window order)
__device__ __nv_bfloat16 g_attn[(size_t)TOK * Cc];    // attention out (bf16, window order)
__device__ float         g_xtok[(size_t)TOK * Cc];    // raw x (fp32, token order)
// transposed bf16 weights [N][K]
__device__ __nv_bfloat16 g_wq[384 * 128];
__device__ __nv_bfloat16 g_wp[128 * 128];
__device__ __nv_bfloat16 g_w1[512 * 128];
__device__ __nv_bfloat16 g_w2[128 * 512];

// ---------------- helpers ----------------
__device__ __forceinline__ uint32_t smem_u32(const void* p) {
    uint32_t a;
    asm("{ .reg .u64 t; cvta.to.shared.u64 t, %1; cvt.u32.u64 %0, t; }" : "=r"(a) : "l"(p));
    return a;
}
__device__ __forceinline__ void ldsm4(uint32_t* r, uint32_t addr) {
    asm volatile("ldmatrix.sync.aligned.m8n8.x4.shared.b16 {%0,%1,%2,%3}, [%4];"
        : "=r"(r[0]), "=r"(r[1]), "=r"(r[2]), "=r"(r[3]) : "r"(addr));
}
__device__ __forceinline__ void ldsm4t(uint32_t* r, uint32_t addr) {
    asm volatile("ldmatrix.sync.aligned.m8n8.x4.trans.shared.b16 {%0,%1,%2,%3}, [%4];"
        : "=r"(r[0]), "=r"(r[1]), "=r"(r[2]), "=r"(r[3]) : "r"(addr));
}
__device__ __forceinline__ void mma_bf16(float* d, const uint32_t* a, uint32_t b0, uint32_t b1) {
    asm volatile(
        "mma.sync.aligned.m16n8k16.row.col.f32.bf16.bf16.f32 "
        "{%0,%1,%2,%3}, {%4,%5,%6,%7}, {%8,%9}, {%0,%1,%2,%3};"
        : "+f"(d[0]), "+f"(d[1]), "+f"(d[2]), "+f"(d[3])
        : "r"(a[0]), "r"(a[1]), "r"(a[2]), "r"(a[3]), "r"(b0), "r"(b1));
}
__device__ __forceinline__ uint32_t pk_bf2(float x, float y) {
    __nv_bfloat162 h = __floats2bfloat162_rn(x, y);
    return *(uint32_t*)&h;
}
__device__ __forceinline__ float gelu_exact(float v) {
    return 0.5f * v * (1.0f + erff(v * 0.7071067811865475f));
}
__device__ __forceinline__ void cpa16(uint32_t dst, const void* src) {
    asm volatile("cp.async.cg.shared.global [%0], [%1], 16;" :: "r"(dst), "l"(src));
}

// 128x128x128 HMMA accumulate: rows at stride 272B. acc flattened [16][4].
__device__ __forceinline__ void tile_mma_128(
    uint32_t sA, uint32_t sW, float (*acc)[4],
    int wm, int wn, int aRow, int aKH, int bRow, int bKH)
{
#pragma unroll
    for (int ks = 0; ks < 8; ks++) {
        const int kk = ks * 16;
        uint32_t a[2][4], b[4][4];
#pragma unroll
        for (int mt = 0; mt < 2; mt++)
            ldsm4(a[mt], sA + (wm * 32 + mt * 16 + aRow) * 272 + (kk + aKH * 8) * 2);
#pragma unroll
        for (int np = 0; np < 4; np++)
            ldsm4(b[np], sW + (wn * 64 + np * 16 + bRow) * 272 + (kk + bKH * 8) * 2);
#pragma unroll
        for (int mt = 0; mt < 2; mt++)
#pragma unroll
            for (int nt = 0; nt < 8; nt++)
                mma_bf16(acc[mt * 8 + nt], a[mt], b[nt >> 1][(nt & 1) * 2],
                         b[nt >> 1][(nt & 1) * 2 + 1]);
    }
}

// ============================================================
// Weight transpose + bf16 convert: W[K][N] -> Wt[N][K] bf16
// ============================================================
__global__ __launch_bounds__(256) void wprep_kernel(
    const float* __restrict__ qkv_w, const float* __restrict__ proj_w,
    const float* __restrict__ fc1_w, const float* __restrict__ fc2_w)
{
    int i = blockIdx.x * 256 + threadIdx.x;
    if (i < 49152) {                       // qkv: 384x128
        int n = i >> 7, k = i & 127;
        g_wq[i] = __float2bfloat16_rn(qkv_w[k * 384 + n]);
    } else if (i < 65536) {                // proj: 128x128
        int j = i - 49152; int n = j >> 7, k = j & 127;
        g_wp[j] = __float2bfloat16_rn(proj_w[k * 128 + n]);
    } else if (i < 131072) {               // fc1: 512x128
        int j = i - 65536; int n = j >> 7, k = j & 127;
        g_w1[j] = __float2bfloat16_rn(fc1_w[k * 512 + n]);
    } else if (i < 196608) {               // fc2: 128x512
        int j = i - 131072; int n = j >> 9, k = j & 511;
        g_w2[j] = __float2bfloat16_rn(fc2_w[k * 128 + n]);
    }
}

// ============================================================
// BN + window partition (bf16) + token-major raw copy (fp32)
// ============================================================
__global__ __launch_bounds__(256) void bn_window_kernel(
    const float* __restrict__ x, const float* __restrict__ gamma,
    const float* __restrict__ beta, const float* __restrict__ mean,
    const float* __restrict__ var, __nv_bfloat16* __restrict__ win,
    float* __restrict__ xtok)
{
    __shared__ float rawS[32][57];
    __shared__ float bnS[32][57];
    const int gx = blockIdx.x;
    const int t = gx / 56, h = gx % 56;
    const int c0 = blockIdx.y * 32;
    const int b = blockIdx.z;
    const int tid = threadIdx.x;

#pragma unroll
    for (int it = 0; it < 7; it++) {
        int idx = tid + it * 256;
        int i = idx / 56, j = idx % 56;
        int c = c0 + i;
        size_t off = ((((size_t)b * Cc + c) * Tt + t) * Hh + h) * Ww + j;
        float v = x[off];
        rawS[i][j] = v;
        float inv = rsqrtf(var[c] + 1e-5f);
        bnS[i][j] = (v - mean[c]) * (inv * gamma[c]) + beta[c];
    }
    __syncthreads();

    const int tblk = t >> 2, wt = t & 3;
    const int hblk = h / 7, wh = h % 7;
#pragma unroll
    for (int it = 0; it < 7; it++) {
        int idx = tid + it * 256;
        int i = idx & 31, j = idx >> 5;
        int wblk = j / 7, ww2 = j % 7;
        int widx = ((b * 4 + tblk) * 8 + hblk) * 8 + wblk;
        int n = (wt * 7 + wh) * 7 + ww2;
        win[((size_t)widx * NTOK + n) * Cc + c0 + i] = __float2bfloat16_rn(bnS[i][j]);
        size_t tok = (size_t)b * THW + ((size_t)t * Hh + h) * Ww + j;
        xtok[tok * Cc + c0 + i] = rawS[i][j];
    }
}

// ============================================================
// QKV GEMM: A staged ONCE per CTA, in-CTA loop over 3 N-blocks,
// B halves (128n x 64k) double-buffered. grid 1568, 8 warps 4Mx2N.
// ============================================================
__global__ __launch_bounds__(256) void qkv_gemm(
    const __nv_bfloat16* __restrict__ A, const __nv_bfloat16* __restrict__ Bm,
    const float* __restrict__ bias, __nv_bfloat16* __restrict__ outq)
{
    extern __shared__ char dsm[];
    const uint32_t sA = smem_u32(dsm);            // [128][136] bf16 (272B rows)
    const uint32_t sB0 = sA + 34816;              // [128][72] bf16 (144B rows)
    const uint32_t sB1 = sB0 + 18432;
    const int tid = threadIdx.x;
    const int rb = blockIdx.x * 128;
    const int lane = tid & 31, wid = tid >> 5;
    const int wm = wid >> 1, wn = wid & 1;

    const int aRow = lane & 15, aKH = lane >> 4;
    const int bRow = ((lane >> 4) << 3) + (lane & 7);
    const int bKH = (lane >> 3) & 1;
    const int gid = lane >> 2, tig = lane & 3;

#pragma unroll
    for (int it = 0; it < 8; it++) {
        int idx = tid + it * 256;
        int row = idx >> 4, c8 = idx & 15;
        cpa16(sA + row * 272 + c8 * 16, A + (size_t)(rb + row) * Cc + c8 * 8);
    }
    asm volatile("cp.async.commit_group;");

    auto load_half = [&](int i, uint32_t buf) {   // i = n*2 + kh
        const int n = i >> 1, kh = i & 1;
#pragma unroll
        for (int it = 0; it < 4; it++) {
            int idx = tid + it * 256;
            int row = idx >> 3, c8 = idx & 7;
            cpa16(buf + row * 144 + c8 * 16,
                  Bm + (size_t)(n * 128 + row) * Cc + kh * 64 + c8 * 8);
        }
        asm volatile("cp.async.commit_group;");
    };
    load_half(0, sB0);

    float acc[16][4];
#pragma unroll
    for (int u = 0; u < 16; u++)
#pragma unroll
        for (int j = 0; j < 4; j++) acc[u][j] = 0.f;

    for (int i = 0; i < 6; i++) {
        const int kh = i & 1;
        __syncthreads();
        if (i < 5) load_half(i + 1, (i + 1) & 1 ? sB1 : sB0);
        if (i < 5) { asm volatile("cp.async.wait_group 1;"); }
        else       { asm volatile("cp.async.wait_group 0;"); }
        __syncthreads();

        const uint32_t bB = (i & 1) ? sB1 : sB0;
#pragma unroll
        for (int ks = 0; ks < 4; ks++) {
            const int kkA = kh * 64 + ks * 16, kkB = ks * 16;
            uint32_t a[2][4], b[4][4];
#pragma unroll
            for (int mt = 0; mt < 2; mt++)
                ldsm4(a[mt], sA + (wm * 32 + mt * 16 + aRow) * 272 + (kkA + aKH * 8) * 2);
#pragma unroll
            for (int np = 0; np < 4; np++)
                ldsm4(b[np], bB + (wn * 64 + np * 16 + bRow) * 144 + (kkB + bKH * 8) * 2);
#pragma unroll
            for (int mt = 0; mt < 2; mt++)
#pragma unroll
                for (int nt = 0; nt < 8; nt++)
                    mma_bf16(acc[mt * 8 + nt], a[mt], b[nt >> 1][(nt & 1) * 2],
                             b[nt >> 1][(nt & 1) * 2 + 1]);
        }

        if (kh == 1) {
            const int n = i >> 1;
#pragma unroll
            for (int mt = 0; mt < 2; mt++) {
#pragma unroll
                for (int half = 0; half < 2; half++) {
                    const int R = rb + wm * 32 + mt * 16 + half * 8 + gid;
                    __nv_bfloat16* po = outq + (size_t)R * 384 + n * 128;
#pragma unroll
                    for (int nt = 0; nt < 8; nt++) {
                        int c = wn * 64 + nt * 8 + tig * 2;
                        float v0 = acc[mt * 8 + nt][half * 2]     + bias[n * 128 + c];
                        float v1 = acc[mt * 8 + nt][half * 2 + 1] + bias[n * 128 + c + 1];
                        *(__nv_bfloat162*)(po + c) = __floats2bfloat162_rn(v0, v1);
                    }
                }
            }
#pragma unroll
            for (int u = 0; u < 16; u++)
#pragma unroll
                for (int j = 0; j < 4; j++) acc[u][j] = 0.f;
        }
    }
}

// ============================================================
// FUSED proj + LayerNorm + MLP + residuals + transposed store.
// One CTA per 128 window-order rows (grid 1568, 256 thr, 104KB smem,
// 2 CTA/SM). y stays in oacc; f in smem. w1[0] prefetched behind
// phase B; w2 loads hidden behind the gelu/erf epilogue.
// ============================================================
__global__ __launch_bounds__(256, 1) void pm_kernel(
    const __nv_bfloat16* __restrict__ A, const __nv_bfloat16* __restrict__ Wp,
    const float* __restrict__ pbias, const float* __restrict__ xres,
    const float* __restrict__ lng, const float* __restrict__ lnb,
    const __nv_bfloat16* __restrict__ w1, const __nv_bfloat16* __restrict__ w2,
    const float* __restrict__ b1, const float* __restrict__ b2,
    float* __restrict__ out)
{
    extern __shared__ char dsm[];
    const uint32_t sF = smem_u32(dsm);            // [128][136] bf16
    const uint32_t sW = sF + 34816;               // weight chunk buffer
    const uint32_t sH = sW + 34816;               // hidden tile
    float2* red = (float2*)(dsm + 104448);        // [128][2]
    const int tid = threadIdx.x;
    const int rb = blockIdx.x * 128;
    const int lane = tid & 31, wid = tid >> 5;
    const int wm = wid >> 1, wn = wid & 1;

    const int aRow = lane & 15, aKH = lane >> 4;
    const int bRow = ((lane >> 4) << 3) + (lane & 7);
    const int bKH = (lane >> 3) & 1;
    const int gid = lane >> 2, tig = lane & 3;
    const int ldRow = tid >> 2, ldC = tid & 3;

    // ---------- phase A: proj GEMM (2-stage, K-chunk 32; aliases sF/sW) ----------
    const uint32_t pA = sF, pB = sF + 20480;
    float oacc[16][4];
#pragma unroll
    for (int u = 0; u < 16; u++)
#pragma unroll
        for (int j = 0; j < 4; j++) oacc[u][j] = 0.f;

    auto preload = [&](int ch) {
        const int b = ch & 1, k0 = ch * 32;
#pragma unroll
        for (int p = 0; p < 2; p++) {
            int row = ldRow + p * 64;
            uint32_t off = (uint32_t)(b * 10240 + row * 80 + ldC * 16);
            cpa16(pA + off, A + (size_t)(rb + row) * Cc + k0 + ldC * 8);
            cpa16(pB + off, Wp + (size_t)row * Cc + k0 + ldC * 8);
        }
        asm volatile("cp.async.commit_group;");
    };

    preload(0);
    for (int ch = 0; ch < 4; ch++) {
        if (ch + 1 < 4) {
            preload(ch + 1);
            asm volatile("cp.async.wait_group 1;");
        } else {
            asm volatile("cp.async.wait_group 0;");
        }
        __syncthreads();
        const uint32_t bA = pA + (ch & 1) * 10240;
        const uint32_t bB = pB + (ch & 1) * 10240;
#pragma unroll
        for (int ks = 0; ks < 2; ks++) {
            const int kk = ks * 16;
            uint32_t a[2][4], b[4][4];
#pragma unroll
            for (int mt = 0; mt < 2; mt++)
                ldsm4(a[mt], bA + (wm * 32 + mt * 16 + aRow) * 80 + (kk + aKH * 8) * 2);
#pragma unroll
            for (int np = 0; np < 4; np++)
                ldsm4(b[np], bB + (wn * 64 + np * 16 + bRow) * 80 + (kk + bKH * 8) * 2);
#pragma unroll
            for (int mt = 0; mt < 2; mt++)
#pragma unroll
                for (int nt = 0; nt < 8; nt++)
                    mma_bf16(oacc[mt * 8 + nt], a[mt], b[nt >> 1][(nt & 1) * 2],
                             b[nt >> 1][(nt & 1) * 2 + 1]);
        }
        __syncthreads();
    }
    // NOTE: proj used sF[0..20480) + [20480..40960); sW region free beyond proj
    // buffers after the final sync above EXCEPT bytes [34816..40960) which
    // overlap pB's second buffer — already consumed (last chunk used bB index
    // (3&1)=1 => pB+10240 = sF+30720..40960; consumed before final sync). Safe.

    // prefetch w1[0] into sW NOW — hides behind the whole of phase B
#pragma unroll
    for (int it = 0; it < 8; it++) {
        int idx = tid + it * 256;
        int row = idx >> 4, c8 = idx & 15;
        cpa16(sW + row * 272 + c8 * 16, w1 + (size_t)row * Cc + c8 * 8);
    }
    asm volatile("cp.async.commit_group;");

    // ---------- phase B: y = proj + bias + x (stays in oacc); LN -> f in sF ----------
    size_t toks[2][2];
    float rsum[2][2], rsq[2][2];
#pragma unroll
    for (int mt = 0; mt < 2; mt++) {
#pragma unroll
        for (int half = 0; half < 2; half++) {
            const int R = rb + wm * 32 + mt * 16 + half * 8 + gid;
            unsigned r = (unsigned)R;
            unsigned widx = r / 196u, nl = r - widx * 196u;
            unsigned wblk = widx & 7u, hblk = (widx >> 3) & 7u;
            unsigned tblk = (widx >> 6) & 3u, bbx = widx >> 8;
            unsigned wt = nl / 49u, rem = nl - wt * 49u;
            unsigned wh = rem / 7u, w2i = rem - wh * 7u;
            unsigned th = tblk * 4 + wt, hp = hblk * 7 + wh, wp = wblk * 7 + w2i;
            size_t tok = (size_t)bbx * THW + ((size_t)th * Hh + hp) * Ww + wp;
            toks[mt][half] = tok;
            const float* pr = xres + tok * Cc;
            float s = 0.f, q = 0.f;
#pragma unroll
            for (int nt = 0; nt < 8; nt++) {
                int c = wn * 64 + nt * 8 + tig * 2;
                float2 xr = *(const float2*)(pr + c);
                float y0 = oacc[mt * 8 + nt][half * 2]     + pbias[c]     + xr.x;
                float y1 = oacc[mt * 8 + nt][half * 2 + 1] + pbias[c + 1] + xr.y;
                oacc[mt * 8 + nt][half * 2]     = y0;
                oacc[mt * 8 + nt][half * 2 + 1] = y1;
                s += y0 + y1;
                q += y0 * y0 + y1 * y1;
            }
            rsum[mt][half] = s; rsq[mt][half] = q;
        }
    }
#pragma unroll
    for (int mt = 0; mt < 2; mt++)
#pragma unroll
        for (int half = 0; half < 2; half++) {
            rsum[mt][half] += __shfl_xor_sync(0xffffffffu, rsum[mt][half], 1);
            rsum[mt][half] += __shfl_xor_sync(0xffffffffu, rsum[mt][half], 2);
            rsq[mt][half]  += __shfl_xor_sync(0xffffffffu, rsq[mt][half], 1);
            rsq[mt][half]  += __shfl_xor_sync(0xffffffffu, rsq[mt][half], 2);
        }
    __syncthreads();
    if (tig == 0) {
#pragma unroll
        for (int mt = 0; mt < 2; mt++)
#pragma unroll
            for (int half = 0; half < 2; half++) {
                int r = wm * 32 + mt * 16 + half * 8 + gid;
                float2 v; v.x = rsum[mt][half]; v.y = rsq[mt][half];
                red[r * 2 + wn] = v;
            }
    }
    __syncthreads();
#pragma unroll
    for (int mt = 0; mt < 2; mt++) {
#pragma unroll
        for (int half = 0; half < 2; half++) {
            int r = wm * 32 + mt * 16 + half * 8 + gid;
            float2 p0 = red[r * 2], p1 = red[r * 2 + 1];
            float mu = (p0.x + p1.x) * (1.f / 128.f);
            float var = (p0.y + p1.y) * (1.f / 128.f) - mu * mu;
            float inv = rsqrtf(var + 1e-5f);
#pragma unroll
            for (int nt = 0; nt < 8; nt++) {
                int c = wn * 64 + nt * 8 + tig * 2;
                float2 gg = *(const float2*)(lng + c);
                float2 bb = *(const float2*)(lnb + c);
                float f0 = (oacc[mt * 8 + nt][half * 2]     - mu) * inv * gg.x + bb.x;
                float f1 = (oacc[mt * 8 + nt][half * 2 + 1] - mu) * inv * gg.y + bb.y;
                uint32_t pk = pk_bf2(f0, f1);
                asm volatile("st.shared.b32 [%0], %1;"
                             :: "r"(sF + r * 272 + c * 2), "r"(pk));
            }
        }
    }
    __syncthreads();

    // ---------- phase C: MLP, oacc (=y) accumulates fc2 ----------
    for (int nc = 0; nc < 4; nc++) {
        if (nc > 0) {
            // w1 chunk (nc=0 already prefetched behind phase B)
#pragma unroll
            for (int it = 0; it < 8; it++) {
                int idx = tid + it * 256;
                int row = idx >> 4, c8 = idx & 15;
                cpa16(sW + row * 272 + c8 * 16,
                      w1 + (size_t)(nc * 128 + row) * Cc + c8 * 8);
            }
            asm volatile("cp.async.commit_group;");
        }
        asm volatile("cp.async.wait_group 0;");
        __syncthreads();

        float hacc[16][4];
#pragma unroll
        for (int u = 0; u < 16; u++)
#pragma unroll
            for (int j = 0; j < 4; j++) hacc[u][j] = 0.f;
        tile_mma_128(sF, sW, hacc, wm, wn, aRow, aKH, bRow, bKH);
        __syncthreads();          // all warps done reading w1 from sW

        // issue w2 load NOW — hides behind the erf-heavy gelu stores below
#pragma unroll
        for (int it = 0; it < 8; it++) {
            int idx = tid + it * 256;
            int row = idx >> 4, c8 = idx & 15;
            cpa16(sW + row * 272 + c8 * 16,
                  w2 + (size_t)row * HID + nc * 128 + c8 * 8);
        }
        asm volatile("cp.async.commit_group;");

#pragma unroll
        for (int mt = 0; mt < 2; mt++) {
#pragma unroll
            for (int half = 0; half < 2; half++) {
                int row = wm * 32 + mt * 16 + half * 8 + gid;
#pragma unroll
                for (int nt = 0; nt < 8; nt++) {
                    int c = wn * 64 + nt * 8 + tig * 2;
                    float v0 = gelu_exact(hacc[mt * 8 + nt][half * 2]     + b1[nc * 128 + c]);
                    float v1 = gelu_exact(hacc[mt * 8 + nt][half * 2 + 1] + b1[nc * 128 + c + 1]);
                    uint32_t pk = pk_bf2(v0, v1);
                    asm volatile("st.shared.b32 [%0], %1;"
                                 :: "r"(sH + row * 272 + c * 2), "r"(pk));
                }
            }
        }
        asm volatile("cp.async.wait_group 0;");
        __syncthreads();          // h visible + w2 ready

        tile_mma_128(sH, sW, oacc, wm, wn, aRow, aKH, bRow, bKH);
        __syncthreads();
    }

    // ---------- phase D: out = oacc + b2, transposed store (B,C,THW) ----------
#pragma unroll
    for (int mt = 0; mt < 2; mt++) {
#pragma unroll
        for (int half = 0; half < 2; half++) {
            size_t tok = toks[mt][half];
            unsigned bq = (unsigned)(tok / (size_t)THW);
            unsigned thw = (unsigned)(tok - (size_t)bq * THW);
#pragma unroll
            for (int nt = 0; nt < 8; nt++) {
                int c = wn * 64 + nt * 8 + tig * 2;
                out[(size_t)(bq * Cc + c) * THW + thw] =
                    oacc[mt * 8 + nt][half * 2] + b2[c];
                out[(size_t)(bq * Cc + c + 1) * THW + thw] =
                    oacc[mt * 8 + nt][half * 2 + 1] + b2[c + 1];
            }
        }
    }
}

// ============================================================
// HMMA attention: one CTA per (window, head), 4 warps (R13 config),
// exp2f with log2e folded into scale.
// ============================================================
__global__ __launch_bounds__(128) void attn_mma_kernel(
    const __nv_bfloat16* __restrict__ qkv, __nv_bfloat16* __restrict__ outp)
{
    __shared__ __nv_bfloat16 Ks[NPAD * SSTR];
    __shared__ __nv_bfloat16 Vs[NPAD * SSTR];
    const int widx = blockIdx.x, hh = blockIdx.y;
    const size_t base = (size_t)widx * NTOK * 384 + hh * 32;
    const int tid = threadIdx.x;
    const int lane = tid & 31, wid = tid >> 5;

    for (int idx = tid; idx < 3136; idx += 128) {
        int row = idx >> 4, u = idx & 15;
        const uint32_t* src = (const uint32_t*)(qkv + base + (size_t)row * 384);
        *(uint32_t*)(Ks + row * SSTR + u * 2) = src[64 + u];
        *(uint32_t*)(Vs + row * SSTR + u * 2) = src[128 + u];
    }
    for (int idx = tid; idx < 12 * 16; idx += 128) {
        int row = 196 + (idx >> 4), u = idx & 15;
        *(uint32_t*)(Ks + row * SSTR + u * 2) = 0;
        *(uint32_t*)(Vs + row * SSTR + u * 2) = 0;
    }
    __syncthreads();

    const int g = lane >> 2, tig = lane & 3;
    const int bRow = ((lane >> 4) << 3) + (lane & 7), bKH = (lane >> 3) & 1;
    const int vKrow = (lane & 7) + ((lane >> 3) & 1) * 8;
    const int vNh = ((lane >> 4) & 1) * 8;
    const float sc2 = 0.17677669529663688f * 1.4426950408889634f;  // 1/sqrt(32)*log2(e)

    for (int mt = wid; mt < 13; mt += 4) {
        const int m0 = mt * 16;
        int r0 = m0 + g;     if (r0 > 195) r0 = 195;
        int r1 = m0 + g + 8; if (r1 > 195) r1 = 195;
        const __nv_bfloat16* q0 = qkv + base + (size_t)r0 * 384 + tig * 2;
        const __nv_bfloat16* q1 = qkv + base + (size_t)r1 * 384 + tig * 2;
        uint32_t qa[2][4];
        qa[0][0] = *(const uint32_t*)(q0);
        qa[0][1] = *(const uint32_t*)(q1);
        qa[0][2] = *(const uint32_t*)(q0 + 8);
        qa[0][3] = *(const uint32_t*)(q1 + 8);
        qa[1][0] = *(const uint32_t*)(q0 + 16);
        qa[1][1] = *(const uint32_t*)(q1 + 16);
        qa[1][2] = *(const uint32_t*)(q0 + 24);
        qa[1][3] = *(const uint32_t*)(q1 + 24);

        float oacc[4][4];
#pragma unroll
        for (int nt = 0; nt < 4; nt++)
#pragma unroll
            for (int j = 0; j < 4; j++) oacc[nt][j] = 0.f;
        float rs0 = 0.f, rs1 = 0.f;

        for (int ks = 0; ks < 13; ks++) {
            uint32_t kb0[4], kb1[4];
            ldsm4(kb0, smem_u32(Ks + (ks * 16 + bRow) * SSTR + bKH * 8));
            ldsm4(kb1, smem_u32(Ks + (ks * 16 + bRow) * SSTR + 16 + bKH * 8));

            float s0[4] = {0.f, 0.f, 0.f, 0.f}, s1[4] = {0.f, 0.f, 0.f, 0.f};
            mma_bf16(s0, qa[0], kb0[0], kb0[1]);
            mma_bf16(s0, qa[1], kb1[0], kb1[1]);
            mma_bf16(s1, qa[0], kb0[2], kb0[3]);
            mma_bf16(s1, qa[1], kb1[2], kb1[3]);

            float e0[4], e1[4];
#pragma unroll
            for (int j = 0; j < 4; j++) {
                e0[j] = exp2f(s0[j] * sc2);
                e1[j] = exp2f(s1[j] * sc2);
            }
            if (ks == 12) {                         // mask cols >= 196
#pragma unroll
                for (int j = 0; j < 4; j++) e1[j] = 0.f;
                if (tig >= 2) {
#pragma unroll
                    for (int j = 0; j < 4; j++) e0[j] = 0.f;
                }
            }
            rs0 += e0[0] + e0[1] + e1[0] + e1[1];
            rs1 += e0[2] + e0[3] + e1[2] + e1[3];

            uint32_t pa[4];
            pa[0] = pk_bf2(e0[0], e0[1]);
            pa[1] = pk_bf2(e0[2], e0[3]);
            pa[2] = pk_bf2(e1[0], e1[1]);
            pa[3] = pk_bf2(e1[2], e1[3]);

            uint32_t vb0[4], vb1[4];
            uint32_t va = smem_u32(Vs + (ks * 16 + vKrow) * SSTR + vNh);
            ldsm4t(vb0, va);
            ldsm4t(vb1, va + 32);
            mma_bf16(oacc[0], pa, vb0[0], vb0[1]);
            mma_bf16(oacc[1], pa, vb0[2], vb0[3]);
            mma_bf16(oacc[2], pa, vb1[0], vb1[1]);
            mma_bf16(oacc[3], pa, vb1[2], vb1[3]);
        }

        rs0 += __shfl_xor_sync(0xffffffffu, rs0, 1);
        rs0 += __shfl_xor_sync(0xffffffffu, rs0, 2);
        rs1 += __shfl_xor_sync(0xffffffffu, rs1, 1);
        rs1 += __shfl_xor_sync(0xffffffffu, rs1, 2);
        float i0 = 1.f / rs0, i1 = 1.f / rs1;

        const int w0 = m0 + g, w1 = m0 + g + 8;
        if (w0 < NTOK) {
            __nv_bfloat16* p = outp + ((size_t)widx * NTOK + w0) * Cc + hh * 32 + tig * 2;
#pragma unroll
            for (int nt = 0; nt < 4; nt++)
                *(__nv_bfloat162*)(p + nt * 8) =
                    __floats2bfloat162_rn(oacc[nt][0] * i0, oacc[nt][1] * i0);
        }
        if (w1 < NTOK) {
            __nv_bfloat16* p = outp + ((size_t)widx * NTOK + w1) * Cc + hh * 32 + tig * 2;
#pragma unroll
            for (int nt = 0; nt < 4; nt++)
                *(__nv_bfloat162*)(p + nt * 8) =
                    __floats2bfloat162_rn(oacc[nt][2] * i1, oacc[nt][3] * i1);
        }
    }
}

// ============================================================
// Launch
// ============================================================
extern "C" void kernel_launch(void* const* d_in, const int* in_sizes, int n_in,
                              void* d_out, int out_size)
{
    const float* x      = (const float*)d_in[0];
    const float* bn_g   = (const float*)d_in[1];
    const float* bn_b   = (const float*)d_in[2];
    const float* bn_m   = (const float*)d_in[3];
    const float* bn_v   = (const float*)d_in[4];
    const float* qkv_w  = (const float*)d_in[5];
    const float* qkv_b  = (const float*)d_in[6];
    const float* proj_w = (const float*)d_in[7];
    const float* proj_b = (const float*)d_in[8];
    const float* ln_g   = (const float*)d_in[9];
    const float* ln_b   = (const float*)d_in[10];
    const float* fc1_w  = (const float*)d_in[11];
    const float* fc1_b  = (const float*)d_in[12];
    const float* fc2_w  = (const float*)d_in[13];
    const float* fc2_b  = (const float*)d_in[14];
    float* out = (float*)d_out;

    __nv_bfloat16 *p_win, *p_qkv, *p_attn, *p_wq, *p_wp, *p_w1, *p_w2;
    float *p_xtok;
    cudaGetSymbolAddress((void**)&p_win, g_win);
    cudaGetSymbolAddress((void**)&p_qkv, g_qkv);
    cudaGetSymbolAddress((void**)&p_attn, g_attn);
    cudaGetSymbolAddress((void**)&p_wq, g_wq);
    cudaGetSymbolAddress((void**)&p_wp, g_wp);
    cudaGetSymbolAddress((void**)&p_w1, g_w1);
    cudaGetSymbolAddress((void**)&p_w2, g_w2);
    cudaGetSymbolAddress((void**)&p_xtok, g_xtok);

    const int QSM = 71680;       // qkv: A once + 2 B-half buffers
    const int FSM = 106496;      // fused pm: sF + sW + sH + red
    cudaFuncSetAttribute(qkv_gemm, cudaFuncAttributeMaxDynamicSharedMemorySize, QSM);
    cudaFuncSetAttribute(pm_kernel, cudaFuncAttributeMaxDynamicSharedMemorySize, FSM);

    // 0. weight transpose + bf16
    wprep_kernel<<<768, 256>>>(qkv_w, proj_w, fc1_w, fc2_w);

    // 1. BN + window partition (bf16) + raw token copy (fp32)
    bn_window_kernel<<<dim3(896, 4, 4), 256>>>(x, bn_g, bn_b, bn_m, bn_v, p_win, p_xtok);

    // 2. QKV GEMM (A staged once, N-loop in-CTA)
    qkv_gemm<<<1568, 256, QSM>>>(p_win, p_wq, qkv_b, p_qkv);

    // 3. Windowed attention (HMMA, 4 warps — reverted to R13 config)
    attn_mma_kernel<<<dim3(1024, 4), 128>>>(p_qkv, p_attn);

    // 4. FUSED proj + LN + MLP + residuals + transposed store
    pm_kernel<<<1568, 256, FSM>>>(p_attn, p_wp, proj_b, p_xtok, ln_g, ln_b,
                                  p_w1, p_w2, fc1_b, fc2_b, out);
}